// round 16
// baseline (speedup 1.0000x reference)
#include <cuda_runtime.h>
#include <cuda_fp16.h>

#define NF    40
#define DIM   64
#define AD    32
#define NP    780
#define NPAD  784         // 49 * 16
#define XSTRH 72          // halves; 144B row stride
#define BLK   128
#define NWARP (BLK / 32)
#define NTILE 49
#define NTPAD 53          // NTILE + NWARP (prefetch padding)
#define OCC   4
#define GRID  (148 * OCC)

__device__ __forceinline__ unsigned h2u(__half2 h) {
    return *reinterpret_cast<unsigned*>(&h);
}
__device__ __forceinline__ __half2 u2h(unsigned u) {
    return *reinterpret_cast<__half2*>(&u);
}

__device__ __forceinline__ void mma_f16(float* acc,
                                        unsigned a0, unsigned a1, unsigned a2, unsigned a3,
                                        unsigned b0, unsigned b1) {
    asm("mma.sync.aligned.m16n8k16.row.col.f32.f16.f16.f32 "
        "{%0,%1,%2,%3}, {%4,%5,%6,%7}, {%8,%9}, {%0,%1,%2,%3};"
        : "+f"(acc[0]), "+f"(acc[1]), "+f"(acc[2]), "+f"(acc[3])
        : "r"(a0), "r"(a1), "r"(a2), "r"(a3), "r"(b0), "r"(b1));
}

// NOT volatile: let ptxas schedule LDSMs across the MMA stream
__device__ __forceinline__ void ldsm_x4(unsigned* r, unsigned addr) {
    asm("ldmatrix.sync.aligned.m8n8.x4.shared.b16 {%0,%1,%2,%3}, [%4];"
        : "=r"(r[0]), "=r"(r[1]), "=r"(r[2]), "=r"(r[3]) : "r"(addr));
}

__global__ __launch_bounds__(BLK, OCC)
void afm_kernel(const float* __restrict__ inputs,   // [B, 40, 64]
                const float* __restrict__ W1,       // [64, 32]
                const float* __restrict__ b1,       // [32]
                const float* __restrict__ w2,       // [32]
                const float* __restrict__ pvec,     // [64]
                float* __restrict__ out,            // [B]
                int B)
{
    __shared__ __align__(16) __half xs[NF * XSTRH];
    __shared__ __align__(16) float lsm4[NPAD][4];     // per-q partial logits
    __shared__ __align__(16) float csm4[NPAD][4];     // per-q partial cp
    __shared__ float red[2 * NWARP + 2];
    __shared__ unsigned short pridx[NP];
    __shared__ uint2 atab[NTPAD][32];                 // per-(tile,lane) smem byte offsets

    const int t    = threadIdx.x;
    const int lane = t & 31;
    const int w    = t >> 5;
    const int q    = lane & 3;
    const int g    = lane >> 2;

    // ================= one-time init (per persistent CTA) =================
    if (t < NF - 1) {
        int i = t;
        int base = i * (2 * NF - 1 - i) / 2;
        for (int j = i + 1; j < NF; j++)
            pridx[base + (j - i - 1)] = (unsigned short)((i << 8) | j);
    }

    // B fragments: W1 only (nt 0..3)
    unsigned bh[4][4][2];
    #pragma unroll
    for (int kt = 0; kt < 4; kt++)
        #pragma unroll
        for (int r = 0; r < 2; r++) {
            const int k0 = kt * 16 + 2 * q + 8 * r;
            #pragma unroll
            for (int nt = 0; nt < 4; nt++) {
                const int n = nt * 8 + g;
                bh[kt][nt][r] = h2u(__floats2half2_rn(W1[k0 * AD + n],
                                                      W1[(k0 + 1) * AD + n]));
            }
        }
    // per-lane p fragments (fp16): ph[kt][0] = cols {2q,2q+1}, ph[kt][1] = {2q+8,2q+9}
    __half2 ph[4][2];
    #pragma unroll
    for (int kt = 0; kt < 4; kt++) {
        const int c0 = kt * 16 + 2 * q;
        ph[kt][0] = __floats2half2_rn(pvec[c0],     pvec[c0 + 1]);
        ph[kt][1] = __floats2half2_rn(pvec[c0 + 8], pvec[c0 + 9]);
    }
    float4 bw[4];
    #pragma unroll
    for (int nt = 0; nt < 4; nt++) {
        const int cc0 = nt * 8 + 2 * q;
        bw[nt] = make_float4(b1[cc0], b1[cc0 + 1], w2[cc0], w2[cc0 + 1]);
    }
    __syncthreads();   // pridx ready

    // precompute LDSM addresses (padded): atab[tile][lane]
    for (int idx = t; idx < NTPAD * 32; idx += BLK) {
        int tile = idx >> 5, ln = idx & 31;
        int pl = tile * 16 + (ln & 15);
        pl = pl < NP ? pl : NP - 1;
        unsigned pp = pridx[pl];
        unsigned koff = (unsigned)(ln >> 4) << 3;
        atab[tile][ln] = make_uint2(2u * ((pp >> 8) * XSTRH + koff),
                                    2u * ((pp & 255u) * XSTRH + koff));
    }
    const unsigned xs_base = (unsigned)__cvta_generic_to_shared(xs);

    // ================= persistent batch loop =================
    for (int bi = blockIdx.x; bi < B; bi += GRID) {
        __syncthreads();   // prev softmax reads done before xs/lsm4 overwrite

        // ---- load + convert this batch row ----
        const float* xin = inputs + (size_t)bi * (NF * DIM);
        #pragma unroll
        for (int idx = t; idx < NF * 16; idx += BLK) {
            int r = idx >> 4, c4 = (idx & 15) << 2;
            float4 v = *(const float4*)(xin + r * 64 + c4);
            *(__half2*)(xs + r * XSTRH + c4)     = __floats2half2_rn(v.x, v.y);
            *(__half2*)(xs + r * XSTRH + c4 + 2) = __floats2half2_rn(v.z, v.w);
        }
        __syncthreads();

        // ---- mainloop (R13 2-stage kt pipeline) ----
        uint2 ao = atab[w][lane];
        for (int tile = w; tile < NTILE; tile += NWARP) {
            const uint2 ao_n = atab[tile + NWARP][lane];
            const unsigned xi_addr = xs_base + ao.x;
            const unsigned xj_addr = xs_base + ao.y;

            // acc init: b1 folded in
            float acc[4][4];
            #pragma unroll
            for (int nt = 0; nt < 4; nt++) {
                acc[nt][0] = bw[nt].x; acc[nt][1] = bw[nt].y;
                acc[nt][2] = bw[nt].x; acc[nt][3] = bw[nt].y;
            }
            // cp accumulators (fp16 chains)
            __half2 cpA0 = __half2half2(__ushort_as_half(0));
            __half2 cpA1 = cpA0, cpB0 = cpA0, cpB1 = cpA0;

            unsigned xi[2][4], xj[2][4];
            ldsm_x4(xi[0], xi_addr);
            ldsm_x4(xj[0], xj_addr);

            #pragma unroll
            for (int kt = 0; kt < 4; kt++) {
                const int cur = kt & 1, nxt = cur ^ 1;
                if (kt < 3) {
                    ldsm_x4(xi[nxt], xi_addr + (kt + 1) * 32);
                    ldsm_x4(xj[nxt], xj_addr + (kt + 1) * 32);
                }
                __half2 pA0 = __hmul2(u2h(xi[cur][0]), u2h(xj[cur][0]));  // row g,  k 2q..
                __half2 pB0 = __hmul2(u2h(xi[cur][1]), u2h(xj[cur][1]));  // row g+8
                __half2 pA8 = __hmul2(u2h(xi[cur][2]), u2h(xj[cur][2]));  // row g,  k 2q+8..
                __half2 pB8 = __hmul2(u2h(xi[cur][3]), u2h(xj[cur][3]));  // row g+8

                // cp on fma pipe (replaces the nt4 MMA)
                cpA0 = __hfma2(pA0, ph[kt][0], cpA0);
                cpA1 = __hfma2(pA8, ph[kt][1], cpA1);
                cpB0 = __hfma2(pB0, ph[kt][0], cpB0);
                cpB1 = __hfma2(pB8, ph[kt][1], cpB1);

                unsigned ah0 = h2u(pA0), ah1 = h2u(pB0);
                unsigned ah2 = h2u(pA8), ah3 = h2u(pB8);
                #pragma unroll
                for (int nt = 0; nt < 4; nt++)
                    mma_f16(acc[nt], ah0, ah1, ah2, ah3, bh[kt][nt][0], bh[kt][nt][1]);
            }

            // epilogue: per-q partial of relu(h) . w2 + cp fold
            float s0 = 0.f, s1 = 0.f;
            #pragma unroll
            for (int nt = 0; nt < 4; nt++) {
                float4 c = bw[nt];
                s0 = fmaf(fmaxf(acc[nt][0], 0.f), c.z, s0);
                s0 = fmaf(fmaxf(acc[nt][1], 0.f), c.w, s0);
                s1 = fmaf(fmaxf(acc[nt][2], 0.f), c.z, s1);
                s1 = fmaf(fmaxf(acc[nt][3], 0.f), c.w, s1);
            }
            float2 fA = __half22float2(__hadd2(cpA0, cpA1));
            float2 fB = __half22float2(__hadd2(cpB0, cpB1));
            const int rowA = tile * 16 + g;
            const int rowB = rowA + 8;
            lsm4[rowA][q] = s0;
            lsm4[rowB][q] = s1;
            csm4[rowA][q] = fA.x + fA.y;
            csm4[rowB][q] = fB.x + fB.y;
            ao = ao_n;
        }
        __syncthreads();

        // ---- one-pass softmax (no max shift; logits are O(1)) ----
        float s = 0.f, ws = 0.f;
        #pragma unroll
        for (int p0 = t; p0 < NP; p0 += BLK) {
            float4 v = *(const float4*)lsm4[p0];
            float4 c = *(const float4*)csm4[p0];
            float e = __expf((v.x + v.y) + (v.z + v.w));
            s += e;
            ws = fmaf(e, (c.x + c.y) + (c.z + c.w), ws);
        }
        #pragma unroll
        for (int o = 16; o; o >>= 1) {
            s  += __shfl_xor_sync(0xffffffffu, s, o);
            ws += __shfl_xor_sync(0xffffffffu, ws, o);
        }
        if (lane == 0) { red[w] = s; red[NWARP + w] = ws; }
        __syncthreads();
        if (t == 0) {
            float S = 0.f, WS = 0.f;
            #pragma unroll
            for (int ww = 0; ww < NWARP; ww++) { S += red[ww]; WS += red[NWARP + ww]; }
            out[bi] = WS / S;
        }
    }
}

extern "C" void kernel_launch(void* const* d_in, const int* in_sizes, int n_in,
                              void* d_out, int out_size)
{
    const float* inputs = (const float*)d_in[0];
    const float* W1     = (const float*)d_in[1];
    const float* b1     = (const float*)d_in[2];
    const float* w2     = (const float*)d_in[3];
    const float* pvec   = (const float*)d_in[4];
    float* out = (float*)d_out;

    int B = in_sizes[0] / (NF * DIM);   // 8192
    int grid = B < GRID ? B : GRID;
    afm_kernel<<<grid, BLK>>>(inputs, W1, b1, w2, pvec, out, B);
}